// round 13
// baseline (speedup 1.0000x reference)
#include <cuda_runtime.h>
#include <cstdint>

#define BB   4
#define CC   128
#define HW   224
#define PHW  7
#define PP   49
#define ALPHA 0.5f

#define N_OUT 25690112ull
#define N_SCC 67108864ull

// smem: F packed (hi,lo) float2 [128][FS2], mu[128], pix[64], EcS [128][72]
#define FS2      68
#define MU_OFF   17408
#define PIX_OFF  17536
#define ECS_OFF  17600
#define ECS_S    72
#define SMEM_FLOATS 26816    // 107264 bytes

__device__ __forceinline__ float tf32_hi(float x) {
    uint32_t r; asm("cvt.rna.tf32.f32 %0, %1;" : "=r"(r) : "f"(x));
    return __uint_as_float(r);
}
__device__ __forceinline__ void split_tf32(float f, uint32_t& h, uint32_t& lo) {
    float hf = tf32_hi(f);
    h  = __float_as_uint(hf);
    lo = __float_as_uint(tf32_hi(f - hf));
}
__device__ __forceinline__ void mma8(float* c,
                                     uint32_t a0, uint32_t a1, uint32_t a2, uint32_t a3,
                                     uint32_t b0, uint32_t b1) {
    asm volatile("mma.sync.aligned.m16n8k8.row.col.f32.tf32.tf32.f32 "
        "{%0,%1,%2,%3}, {%4,%5,%6,%7}, {%8,%9}, {%0,%1,%2,%3};"
        : "+f"(c[0]), "+f"(c[1]), "+f"(c[2]), "+f"(c[3])
        : "r"(a0), "r"(a1), "r"(a2), "r"(a3), "r"(b0), "r"(b1));
}

__global__ __launch_bounds__(256, 2)
void bdca_mma_kernel(const float* __restrict__ x, const float* __restrict__ beta,
                     float* __restrict__ out, float* __restrict__ Sc,
                     float* __restrict__ cov, float* __restrict__ ecmap)
{
    extern __shared__ float sm[];
    float2* F2  = (float2*)sm;         // [128][FS2] packed (hi, lo)
    float*  mu  = sm + MU_OFF;
    int*    pix = (int*)(sm + PIX_OFF);
    float*  EcS = sm + ECS_OFF;        // [128][ECS_S]

    const int tid = threadIdx.x;
    const int w = tid >> 5, l = tid & 31;
    const int g = l >> 2, tg = l & 3;

    const int bm = blockIdx.x;
    const int b  = bm >> 10, m = bm & 1023;
    const int hh = m >> 5, ww = m & 31;
    const size_t xoff = (size_t)b * (CC * HW * HW) + (size_t)(hh * PHW) * HW + (size_t)(ww * PHW);

    // ---- pixel LUT ----
    if (tid < 49) {
        int i = tid / 7, j = tid - 7 * i;
        pix[tid] = i * HW + j;
    }
    __syncthreads();

    // ---- stage F as (hi,lo) pairs; pad pixels 49..55 zero; div-free indexing ----
    for (int idx = tid; idx < CC * 64; idx += 256) {
        int c = idx >> 6, p = idx & 63;
        if (p < 56) {
            float2 v = make_float2(0.f, 0.f);
            if (p < PP) {
                float xv = __ldg(x + xoff + (size_t)c * (HW * HW) + pix[p]);
                float hi = tf32_hi(xv);
                v = make_float2(hi, tf32_hi(xv - hi));
            }
            F2[c * FS2 + p] = v;
        }
    }
    __syncthreads();

    // ---- mu: warp w owns channels 16w..16w+15 ----
    {
        #pragma unroll 4
        for (int cc = 0; cc < 16; cc++) {
            int c = 16 * w + cc;
            float2 v2 = F2[c * FS2 + l];
            float v = v2.x + v2.y;
            if (l < 17) {
                float2 u2 = F2[c * FS2 + 32 + l];
                v += u2.x + u2.y;
            }
            #pragma unroll
            for (int o = 16; o; o >>= 1) v += __shfl_xor_sync(0xffffffffu, v, o);
            if (l == 0) mu[c] = v * (1.f / 49.f);
        }
    }
    __syncthreads();

    const int r1 = 16 * w + g;

    // ---- GEMM1: G = F * F^T, warp strip 16 rows x 128 cols, split tf32 ----
    float acc[16][4];
    #pragma unroll
    for (int n = 0; n < 16; n++)
        #pragma unroll
        for (int j = 0; j < 4; j++) acc[n][j] = 0.f;

    #pragma unroll 1
    for (int k = 0; k < 7; k++) {
        const int ko = 8 * k + tg;
        float2 A0 = F2[r1 * FS2 + ko];
        float2 A1 = F2[(r1 + 8) * FS2 + ko];
        float2 A2 = F2[r1 * FS2 + ko + 4];
        float2 A3 = F2[(r1 + 8) * FS2 + ko + 4];
        uint32_t a0h = __float_as_uint(A0.x), a0l = __float_as_uint(A0.y);
        uint32_t a1h = __float_as_uint(A1.x), a1l = __float_as_uint(A1.y);
        uint32_t a2h = __float_as_uint(A2.x), a2l = __float_as_uint(A2.y);
        uint32_t a3h = __float_as_uint(A3.x), a3l = __float_as_uint(A3.y);
        #pragma unroll
        for (int n = 0; n < 16; n++) {
            const int br = (8 * n + g) * FS2 + ko;
            float2 B0 = F2[br];
            float2 B1 = F2[br + 4];
            uint32_t b0h = __float_as_uint(B0.x), b0l = __float_as_uint(B0.y);
            uint32_t b1h = __float_as_uint(B1.x), b1l = __float_as_uint(B1.y);
            mma8(acc[n], a0h, a1h, a2h, a3h, b0h, b1h);
            mma8(acc[n], a0h, a1h, a2h, a3h, b0l, b1l);
            mma8(acc[n], a0l, a1l, a2l, a3l, b0h, b1h);
        }
    }

    // ---- softmax row stats (rows r1, r1+8) ----
    float mx1 = -3.4e38f, mx2 = -3.4e38f;
    #pragma unroll
    for (int n = 0; n < 16; n++) {
        mx1 = fmaxf(mx1, fmaxf(acc[n][0], acc[n][1]));
        mx2 = fmaxf(mx2, fmaxf(acc[n][2], acc[n][3]));
    }
    mx1 = fmaxf(mx1, __shfl_xor_sync(0xffffffffu, mx1, 1));
    mx1 = fmaxf(mx1, __shfl_xor_sync(0xffffffffu, mx1, 2));
    mx2 = fmaxf(mx2, __shfl_xor_sync(0xffffffffu, mx2, 1));
    mx2 = fmaxf(mx2, __shfl_xor_sync(0xffffffffu, mx2, 2));

    float s1 = 0.f, s2 = 0.f;
    #pragma unroll
    for (int n = 0; n < 16; n++) {
        s1 += __expf(acc[n][0] - mx1) + __expf(acc[n][1] - mx1);
        s2 += __expf(acc[n][2] - mx2) + __expf(acc[n][3] - mx2);
    }
    s1 += __shfl_xor_sync(0xffffffffu, s1, 1);
    s1 += __shfl_xor_sync(0xffffffffu, s1, 2);
    s2 += __shfl_xor_sync(0xffffffffu, s2, 1);
    s2 += __shfl_xor_sync(0xffffffffu, s2, 2);
    const float i1 = 1.f / s1, i2 = 1.f / s2;
    const float m1 = mu[r1], m2 = mu[r1 + 8];

    // ---- epilogue A: Sc/cov to gmem; L replaces G in acc (C-fragment layout) ----
    {
        const size_t ob = (size_t)bm << 14;
        #pragma unroll
        for (int n = 0; n < 16; n++) {
            int col = 8 * n + 2 * tg;
            float2 mc = *(float2*)(mu + col);
            float sc0 = __expf(acc[n][0] - mx1) * i1;
            float sc1 = __expf(acc[n][1] - mx1) * i1;
            float sc2 = __expf(acc[n][2] - mx2) * i2;
            float sc3 = __expf(acc[n][3] - mx2) * i2;
            float cv0 = acc[n][0] * (1.f / 49.f) - m1 * mc.x;
            float cv1 = acc[n][1] * (1.f / 49.f) - m1 * mc.y;
            float cv2 = acc[n][2] * (1.f / 49.f) - m2 * mc.x;
            float cv3 = acc[n][3] * (1.f / 49.f) - m2 * mc.y;
            *(float2*)(Sc  + ob + (size_t)r1 * 128 + col)       = make_float2(sc0, sc1);
            *(float2*)(Sc  + ob + (size_t)(r1 + 8) * 128 + col) = make_float2(sc2, sc3);
            *(float2*)(cov + ob + (size_t)r1 * 128 + col)       = make_float2(cv0, cv1);
            *(float2*)(cov + ob + (size_t)(r1 + 8) * 128 + col) = make_float2(cv2, cv3);
            acc[n][0] = fmaf(ALPHA, cv0, sc0);
            acc[n][1] = fmaf(ALPHA, cv1, sc1);
            acc[n][2] = fmaf(ALPHA, cv2, sc2);
            acc[n][3] = fmaf(ALPHA, cv3, sc3);
        }
    }

    // ---- GEMM2: Ec = L * F. A fragments built from acc via quad shuffles ----
    float acc2[7][4];
    #pragma unroll
    for (int n = 0; n < 7; n++)
        #pragma unroll
        for (int j = 0; j < 4; j++) acc2[n][j] = 0.f;

    const int s0 = (l & 28) | (tg >> 1);
    const bool odd = (tg & 1);

    #pragma unroll
    for (int kk = 0; kk < 16; kk++) {
        float v00 = __shfl_sync(0xffffffffu, acc[kk][0], s0);
        float v01 = __shfl_sync(0xffffffffu, acc[kk][1], s0);
        float v10 = __shfl_sync(0xffffffffu, acc[kk][2], s0);
        float v11 = __shfl_sync(0xffffffffu, acc[kk][3], s0);
        float v20 = __shfl_sync(0xffffffffu, acc[kk][0], s0 + 2);
        float v21 = __shfl_sync(0xffffffffu, acc[kk][1], s0 + 2);
        float v30 = __shfl_sync(0xffffffffu, acc[kk][2], s0 + 2);
        float v31 = __shfl_sync(0xffffffffu, acc[kk][3], s0 + 2);
        float a0f = odd ? v01 : v00;
        float a1f = odd ? v11 : v10;
        float a2f = odd ? v21 : v20;
        float a3f = odd ? v31 : v30;
        uint32_t a0h, a0l, a1h, a1l, a2h, a2l, a3h, a3l;
        split_tf32(a0f, a0h, a0l);
        split_tf32(a1f, a1h, a1l);
        split_tf32(a2f, a2h, a2l);
        split_tf32(a3f, a3h, a3l);
        const int ko = 8 * kk + tg;
        #pragma unroll
        for (int n = 0; n < 7; n++) {
            const int bc = 8 * n + g;
            float2 B0 = F2[ko * FS2 + bc];
            float2 B1 = F2[(ko + 4) * FS2 + bc];
            uint32_t b0h = __float_as_uint(B0.x), b0l = __float_as_uint(B0.y);
            uint32_t b1h = __float_as_uint(B1.x), b1l = __float_as_uint(B1.y);
            mma8(acc2[n], a0h, a1h, a2h, a3h, b0h, b1h);
            mma8(acc2[n], a0h, a1h, a2h, a3h, b0l, b1l);
            mma8(acc2[n], a0l, a1l, a2l, a3l, b0h, b1h);
        }
    }

    // ---- stage Ec into smem (stride 72: conflict-free for C-fragment STS.64) ----
    #pragma unroll
    for (int n = 0; n < 7; n++) {
        const int p0 = 8 * n + 2 * tg;
        *(float2*)(EcS + r1 * ECS_S + p0)       = make_float2(acc2[n][0], acc2[n][1]);
        *(float2*)(EcS + (r1 + 8) * ECS_S + p0) = make_float2(acc2[n][2], acc2[n][3]);
    }
    __syncthreads();

    // ---- epilogue B: coalesced fold + out = x * (beta*Ec + x) ----
    {
        const float beta0 = beta[0];
        for (int idx = tid; idx < CC * 64; idx += 256) {
            int c = idx >> 6, p = idx & 63;
            if (p < PP) {
                float2 xv2 = F2[c * FS2 + p];
                float xv = xv2.x + xv2.y;
                float ec = EcS[c * ECS_S + p];
                size_t ga = xoff + (size_t)c * (HW * HW) + pix[p];
                ecmap[ga] = ec;
                out[ga]   = xv * fmaf(beta0, ec, xv);
            }
        }
    }
}

extern "C" void kernel_launch(void* const* d_in, const int* in_sizes, int n_in,
                              void* d_out, int out_size)
{
    const float* x    = (const float*)d_in[0];
    const float* beta = (const float*)d_in[1];

    float* out   = (float*)d_out;
    float* Sc    = out + N_OUT;
    float* cov   = Sc + N_SCC;
    float* ecmap = cov + N_SCC;

    const int smem_bytes = SMEM_FLOATS * (int)sizeof(float);   // 107264
    cudaFuncSetAttribute(bdca_mma_kernel, cudaFuncAttributeMaxDynamicSharedMemorySize, smem_bytes);
    bdca_mma_kernel<<<BB * 1024, 256, smem_bytes>>>(x, beta, out, Sc, cov, ecmap);
}

// round 14
// speedup vs baseline: 1.1820x; 1.1820x over previous
#include <cuda_runtime.h>
#include <cstdint>

#define BB   4
#define CC   128
#define HW   224
#define PHW  7
#define PP   49
#define ALPHA 0.5f

#define N_OUT 25690112ull
#define N_SCC 67108864ull

// smem: F packed (hi,lo) float2 [128][FS2], mu[128]
#define FS2     68          // float2 stride
#define MU_OFF  17408       // 128*68*2 floats
#define SMEM_FLOATS 17536   // 70144 bytes

__device__ __forceinline__ float tf32_hi(float x) {
    uint32_t r; asm("cvt.rna.tf32.f32 %0, %1;" : "=r"(r) : "f"(x));
    return __uint_as_float(r);
}
__device__ __forceinline__ void mma8(float* c,
                                     uint32_t a0, uint32_t a1, uint32_t a2, uint32_t a3,
                                     uint32_t b0, uint32_t b1) {
    asm volatile("mma.sync.aligned.m16n8k8.row.col.f32.tf32.tf32.f32 "
        "{%0,%1,%2,%3}, {%4,%5,%6,%7}, {%8,%9}, {%0,%1,%2,%3};"
        : "+f"(c[0]), "+f"(c[1]), "+f"(c[2]), "+f"(c[3])
        : "r"(a0), "r"(a1), "r"(a2), "r"(a3), "r"(b0), "r"(b1));
}

__global__ __launch_bounds__(256, 2)
void bdca_mma_kernel(const float* __restrict__ x, const float* __restrict__ beta,
                     float* __restrict__ out, float* __restrict__ Sc,
                     float* __restrict__ cov, float* __restrict__ ecmap)
{
    extern __shared__ float sm[];
    float2* F2 = (float2*)sm;          // [128][FS2] packed (hi, lo)
    float*  mu = sm + MU_OFF;

    const int tid = threadIdx.x;
    const int w = tid >> 5, l = tid & 31;
    const int g = l >> 2, tg = l & 3;

    const int bm = blockIdx.x;
    const int b  = bm >> 10, m = bm & 1023;
    const int hh = m >> 5, ww = m & 31;
    const size_t xoff = (size_t)b * (CC * HW * HW) + (size_t)(hh * PHW) * HW + (size_t)(ww * PHW);

    // ---- zero pad pixels 49..55, stage F as (hi,lo) pairs ----
    for (int t = tid; t < CC * 7; t += 256) {
        int c = t / 7, p = PP + t % 7;
        F2[c * FS2 + p] = make_float2(0.f, 0.f);
    }
    for (int idx = tid; idx < CC * PP; idx += 256) {
        int c = idx / PP, p = idx - c * PP;
        int i = p / PHW, j = p - i * PHW;
        float xv = __ldg(x + xoff + (size_t)c * (HW * HW) + i * HW + j);
        float hi = tf32_hi(xv);
        F2[c * FS2 + p] = make_float2(hi, tf32_hi(xv - hi));
    }
    __syncthreads();

    // ---- mu: warp w owns channels 16w..16w+15 ----
    {
        #pragma unroll 4
        for (int cc = 0; cc < 16; cc++) {
            int c = 16 * w + cc;
            float2 v2 = F2[c * FS2 + l];
            float v = v2.x + v2.y;
            if (l < 17) {
                float2 u2 = F2[c * FS2 + 32 + l];
                v += u2.x + u2.y;
            }
            #pragma unroll
            for (int o = 16; o; o >>= 1) v += __shfl_xor_sync(0xffffffffu, v, o);
            if (l == 0) mu[c] = v * (1.f / 49.f);
        }
    }
    __syncthreads();

    const int r1 = 16 * w + g;

    // ---- GEMM1: G = F * F^T, warp strip 16 rows x 128 cols, split tf32 (3-term) ----
    float acc[16][4];
    #pragma unroll
    for (int n = 0; n < 16; n++)
        #pragma unroll
        for (int j = 0; j < 4; j++) acc[n][j] = 0.f;

    #pragma unroll 1
    for (int k = 0; k < 7; k++) {
        const int ko = 8 * k + tg;
        float2 A0 = F2[r1 * FS2 + ko];
        float2 A1 = F2[(r1 + 8) * FS2 + ko];
        float2 A2 = F2[r1 * FS2 + ko + 4];
        float2 A3 = F2[(r1 + 8) * FS2 + ko + 4];
        uint32_t a0h = __float_as_uint(A0.x), a0l = __float_as_uint(A0.y);
        uint32_t a1h = __float_as_uint(A1.x), a1l = __float_as_uint(A1.y);
        uint32_t a2h = __float_as_uint(A2.x), a2l = __float_as_uint(A2.y);
        uint32_t a3h = __float_as_uint(A3.x), a3l = __float_as_uint(A3.y);
        #pragma unroll
        for (int n = 0; n < 16; n++) {
            const int br = (8 * n + g) * FS2 + ko;
            float2 B0 = F2[br];
            float2 B1 = F2[br + 4];
            uint32_t b0h = __float_as_uint(B0.x), b0l = __float_as_uint(B0.y);
            uint32_t b1h = __float_as_uint(B1.x), b1l = __float_as_uint(B1.y);
            mma8(acc[n], a0h, a1h, a2h, a3h, b0h, b1h);
            mma8(acc[n], a0h, a1h, a2h, a3h, b0l, b1l);
            mma8(acc[n], a0l, a1l, a2l, a3l, b0h, b1h);
        }
    }

    // ---- softmax row stats (rows r1, r1+8) ----
    float mx1 = -3.4e38f, mx2 = -3.4e38f;
    #pragma unroll
    for (int n = 0; n < 16; n++) {
        mx1 = fmaxf(mx1, fmaxf(acc[n][0], acc[n][1]));
        mx2 = fmaxf(mx2, fmaxf(acc[n][2], acc[n][3]));
    }
    mx1 = fmaxf(mx1, __shfl_xor_sync(0xffffffffu, mx1, 1));
    mx1 = fmaxf(mx1, __shfl_xor_sync(0xffffffffu, mx1, 2));
    mx2 = fmaxf(mx2, __shfl_xor_sync(0xffffffffu, mx2, 1));
    mx2 = fmaxf(mx2, __shfl_xor_sync(0xffffffffu, mx2, 2));

    float s1 = 0.f, s2 = 0.f;
    #pragma unroll
    for (int n = 0; n < 16; n++) {
        s1 += __expf(acc[n][0] - mx1) + __expf(acc[n][1] - mx1);
        s2 += __expf(acc[n][2] - mx2) + __expf(acc[n][3] - mx2);
    }
    s1 += __shfl_xor_sync(0xffffffffu, s1, 1);
    s1 += __shfl_xor_sync(0xffffffffu, s1, 2);
    s2 += __shfl_xor_sync(0xffffffffu, s2, 1);
    s2 += __shfl_xor_sync(0xffffffffu, s2, 2);
    const float i1 = 1.f / s1, i2 = 1.f / s2;
    const float m1 = mu[r1], m2 = mu[r1 + 8];

    // ---- epilogue A: Sc/cov to gmem; L replaces G in acc (C-fragment layout) ----
    {
        const size_t ob = (size_t)bm << 14;
        #pragma unroll
        for (int n = 0; n < 16; n++) {
            int col = 8 * n + 2 * tg;
            float2 mc = *(float2*)(mu + col);
            float sc0 = __expf(acc[n][0] - mx1) * i1;
            float sc1 = __expf(acc[n][1] - mx1) * i1;
            float sc2 = __expf(acc[n][2] - mx2) * i2;
            float sc3 = __expf(acc[n][3] - mx2) * i2;
            float cv0 = acc[n][0] * (1.f / 49.f) - m1 * mc.x;
            float cv1 = acc[n][1] * (1.f / 49.f) - m1 * mc.y;
            float cv2 = acc[n][2] * (1.f / 49.f) - m2 * mc.x;
            float cv3 = acc[n][3] * (1.f / 49.f) - m2 * mc.y;
            *(float2*)(Sc  + ob + (size_t)r1 * 128 + col)       = make_float2(sc0, sc1);
            *(float2*)(Sc  + ob + (size_t)(r1 + 8) * 128 + col) = make_float2(sc2, sc3);
            *(float2*)(cov + ob + (size_t)r1 * 128 + col)       = make_float2(cv0, cv1);
            *(float2*)(cov + ob + (size_t)(r1 + 8) * 128 + col) = make_float2(cv2, cv3);
            acc[n][0] = fmaf(ALPHA, cv0, sc0);
            acc[n][1] = fmaf(ALPHA, cv1, sc1);
            acc[n][2] = fmaf(ALPHA, cv2, sc2);
            acc[n][3] = fmaf(ALPHA, cv3, sc3);
        }
    }

    // ---- GEMM2 (2-term): Ec = L_hi * (F_hi + F_lo). A from acc via quad shuffles ----
    float acc2[7][4];
    #pragma unroll
    for (int n = 0; n < 7; n++)
        #pragma unroll
        for (int j = 0; j < 4; j++) acc2[n][j] = 0.f;

    const int s0 = (l & 28) | (tg >> 1);
    const bool odd = (tg & 1);

    #pragma unroll
    for (int kk = 0; kk < 16; kk++) {
        float v00 = __shfl_sync(0xffffffffu, acc[kk][0], s0);
        float v01 = __shfl_sync(0xffffffffu, acc[kk][1], s0);
        float v10 = __shfl_sync(0xffffffffu, acc[kk][2], s0);
        float v11 = __shfl_sync(0xffffffffu, acc[kk][3], s0);
        float v20 = __shfl_sync(0xffffffffu, acc[kk][0], s0 + 2);
        float v21 = __shfl_sync(0xffffffffu, acc[kk][1], s0 + 2);
        float v30 = __shfl_sync(0xffffffffu, acc[kk][2], s0 + 2);
        float v31 = __shfl_sync(0xffffffffu, acc[kk][3], s0 + 2);
        uint32_t a0h = __float_as_uint(tf32_hi(odd ? v01 : v00));
        uint32_t a1h = __float_as_uint(tf32_hi(odd ? v11 : v10));
        uint32_t a2h = __float_as_uint(tf32_hi(odd ? v21 : v20));
        uint32_t a3h = __float_as_uint(tf32_hi(odd ? v31 : v30));
        const int ko = 8 * kk + tg;
        #pragma unroll
        for (int n = 0; n < 7; n++) {
            const int bc = 8 * n + g;
            float2 B0 = F2[ko * FS2 + bc];
            float2 B1 = F2[(ko + 4) * FS2 + bc];
            uint32_t b0h = __float_as_uint(B0.x), b0l = __float_as_uint(B0.y);
            uint32_t b1h = __float_as_uint(B1.x), b1l = __float_as_uint(B1.y);
            mma8(acc2[n], a0h, a1h, a2h, a3h, b0h, b1h);
            mma8(acc2[n], a0h, a1h, a2h, a3h, b0l, b1l);
        }
    }

    // ---- epilogue B: fold Ec, out = x * (beta*Ec + x) ----
    {
        const float beta0 = beta[0];
        #pragma unroll
        for (int n = 0; n < 7; n++) {
            const int p0 = 8 * n + 2 * tg;
            #pragma unroll
            for (int e = 0; e < 4; e++) {
                int p = p0 + (e & 1);
                int c = (e < 2) ? r1 : (r1 + 8);
                if (p < PP) {
                    float2 xv2 = F2[c * FS2 + p];
                    float xv = xv2.x + xv2.y;
                    float ec = acc2[n][e];
                    int i = p / PHW, j = p - i * PHW;
                    size_t ga = xoff + (size_t)c * (HW * HW) + i * HW + j;
                    ecmap[ga] = ec;
                    out[ga]   = xv * fmaf(beta0, ec, xv);
                }
            }
        }
    }
}

extern "C" void kernel_launch(void* const* d_in, const int* in_sizes, int n_in,
                              void* d_out, int out_size)
{
    const float* x    = (const float*)d_in[0];
    const float* beta = (const float*)d_in[1];

    float* out   = (float*)d_out;
    float* Sc    = out + N_OUT;
    float* cov   = Sc + N_SCC;
    float* ecmap = cov + N_SCC;

    const int smem_bytes = SMEM_FLOATS * (int)sizeof(float);   // 70144
    cudaFuncSetAttribute(bdca_mma_kernel, cudaFuncAttributeMaxDynamicSharedMemorySize, smem_bytes);
    bdca_mma_kernel<<<BB * 1024, 256, smem_bytes>>>(x, beta, out, Sc, cov, ecmap);
}

// round 15
// speedup vs baseline: 1.3413x; 1.1348x over previous
#include <cuda_runtime.h>
#include <cstdint>

#define BB   4
#define CC   128
#define HW   224
#define PHW  7
#define PP   49
#define ALPHA 0.5f

#define N_OUT 25690112ull
#define N_SCC 67108864ull

// smem (bytes): Fb0[128][72]bf16, Fb1 same, Ft0[56][136]bf16, Ft1 same, mu[128]f32
#define FSB   72          // F bf16 row stride (144B, ==16 mod 128)
#define FSW   36          // F u32 row stride
#define STB   136         // Ft bf16 row stride (272B, ==16 mod 128)
#define STW   68
#define OFF_FB1  18432
#define OFF_FT0  36864
#define OFF_FT1  52096
#define OFF_MU   67328
#define SMEM_BYTES 67840

__device__ __forceinline__ uint16_t f2bf(float x) {
    uint16_t r; asm("cvt.rn.bf16.f32 %0, %1;" : "=h"(r) : "f"(x)); return r;
}
__device__ __forceinline__ float bf2f(uint16_t b) {
    return __uint_as_float(((uint32_t)b) << 16);
}
// pack (lo, hi) floats -> bf16x2 reg (lo in low 16 bits)
__device__ __forceinline__ uint32_t packbf(float lo, float hi) {
    uint32_t r; asm("cvt.rn.bf16x2.f32 %0, %1, %2;" : "=r"(r) : "f"(hi), "f"(lo)); return r;
}
__device__ __forceinline__ float lof(uint32_t r) { return __uint_as_float(r << 16); }
__device__ __forceinline__ float hif(uint32_t r) { return __uint_as_float(r & 0xffff0000u); }

__device__ __forceinline__ void mma16(float* c,
                                      uint32_t a0, uint32_t a1, uint32_t a2, uint32_t a3,
                                      uint32_t b0, uint32_t b1) {
    asm volatile("mma.sync.aligned.m16n8k16.row.col.f32.bf16.bf16.f32 "
        "{%0,%1,%2,%3}, {%4,%5,%6,%7}, {%8,%9}, {%0,%1,%2,%3};"
        : "+f"(c[0]), "+f"(c[1]), "+f"(c[2]), "+f"(c[3])
        : "r"(a0), "r"(a1), "r"(a2), "r"(a3), "r"(b0), "r"(b1));
}

__global__ __launch_bounds__(256, 2)
void bdca_mma_kernel(const float* __restrict__ x, const float* __restrict__ beta,
                     float* __restrict__ out, float* __restrict__ Sc,
                     float* __restrict__ cov, float* __restrict__ ecmap)
{
    extern __shared__ char sm[];
    uint16_t* Fb0 = (uint16_t*)sm;
    uint16_t* Fb1 = (uint16_t*)(sm + OFF_FB1);
    uint16_t* Ft0 = (uint16_t*)(sm + OFF_FT0);
    uint16_t* Ft1 = (uint16_t*)(sm + OFF_FT1);
    float*    mu  = (float*)(sm + OFF_MU);
    const uint32_t* F0w = (const uint32_t*)sm;
    const uint32_t* F1w = (const uint32_t*)(sm + OFF_FB1);
    const uint32_t* T0w = (const uint32_t*)(sm + OFF_FT0);
    const uint32_t* T1w = (const uint32_t*)(sm + OFF_FT1);

    const int tid = threadIdx.x;
    const int w = tid >> 5, l = tid & 31;
    const int g = l >> 2, tg = l & 3;

    const int bm = blockIdx.x;
    const int b  = bm >> 10, m = bm & 1023;
    const int hh = m >> 5, ww = m & 31;
    const size_t xoff = (size_t)b * (CC * HW * HW) + (size_t)(hh * PHW) * HW + (size_t)(ww * PHW);

    // ---- stage: x -> bf16 (b0,b1) into F [c][p] (pad p 49..63 = 0) and Ft [p][c] ----
    for (int idx = tid; idx < CC * 64; idx += 256) {
        int c = idx >> 6, p = idx & 63;
        float xv = 0.f;
        if (p < PP) {
            int i = p / PHW, j = p - i * PHW;
            xv = __ldg(x + xoff + (size_t)c * (HW * HW) + i * HW + j);
        }
        uint16_t b0 = f2bf(xv);
        uint16_t b1 = f2bf(xv - bf2f(b0));
        Fb0[c * FSB + p] = b0;
        Fb1[c * FSB + p] = b1;
        if (p < 56) {
            Ft0[p * STB + c] = b0;
            Ft1[p * STB + c] = b1;
        }
    }
    __syncthreads();

    // ---- mu: warp w owns channels 16w..16w+15 ----
    {
        #pragma unroll 4
        for (int cc = 0; cc < 16; cc++) {
            int c = 16 * w + cc;
            float v = bf2f(Fb0[c * FSB + l]) + bf2f(Fb1[c * FSB + l]);
            if (l < 17) v += bf2f(Fb0[c * FSB + 32 + l]) + bf2f(Fb1[c * FSB + 32 + l]);
            #pragma unroll
            for (int o = 16; o; o >>= 1) v += __shfl_xor_sync(0xffffffffu, v, o);
            if (l == 0) mu[c] = v * (1.f / 49.f);
        }
    }
    __syncthreads();

    const int r1 = 16 * w + g;

    // ---- GEMM1: G = F * F^T, 4 K16 tiles, 3-product bf16 split ----
    float acc[16][4];
    #pragma unroll
    for (int n = 0; n < 16; n++)
        #pragma unroll
        for (int j = 0; j < 4; j++) acc[n][j] = 0.f;

    #pragma unroll 1
    for (int kt = 0; kt < 4; kt++) {
        const int ka = 8 * kt + tg;   // u32 index within row (covers bf16 cols 16kt+2tg,+1)
        uint32_t a00 = F0w[r1 * FSW + ka],     a01 = F0w[(r1 + 8) * FSW + ka];
        uint32_t a02 = F0w[r1 * FSW + ka + 4], a03 = F0w[(r1 + 8) * FSW + ka + 4];
        uint32_t a10 = F1w[r1 * FSW + ka],     a11 = F1w[(r1 + 8) * FSW + ka];
        uint32_t a12 = F1w[r1 * FSW + ka + 4], a13 = F1w[(r1 + 8) * FSW + ka + 4];
        #pragma unroll
        for (int n = 0; n < 16; n++) {
            const int bb = (8 * n + g) * FSW + ka;
            uint32_t b00 = F0w[bb], b01 = F0w[bb + 4];
            uint32_t b10 = F1w[bb], b11 = F1w[bb + 4];
            mma16(acc[n], a00, a01, a02, a03, b00, b01);
            mma16(acc[n], a00, a01, a02, a03, b10, b11);
            mma16(acc[n], a10, a11, a12, a13, b00, b01);
        }
    }

    // ---- softmax row stats (rows r1, r1+8) ----
    float mx1 = -3.4e38f, mx2 = -3.4e38f;
    #pragma unroll
    for (int n = 0; n < 16; n++) {
        mx1 = fmaxf(mx1, fmaxf(acc[n][0], acc[n][1]));
        mx2 = fmaxf(mx2, fmaxf(acc[n][2], acc[n][3]));
    }
    mx1 = fmaxf(mx1, __shfl_xor_sync(0xffffffffu, mx1, 1));
    mx1 = fmaxf(mx1, __shfl_xor_sync(0xffffffffu, mx1, 2));
    mx2 = fmaxf(mx2, __shfl_xor_sync(0xffffffffu, mx2, 1));
    mx2 = fmaxf(mx2, __shfl_xor_sync(0xffffffffu, mx2, 2));

    float s1 = 0.f, s2 = 0.f;
    #pragma unroll
    for (int n = 0; n < 16; n++) {
        s1 += __expf(acc[n][0] - mx1) + __expf(acc[n][1] - mx1);
        s2 += __expf(acc[n][2] - mx2) + __expf(acc[n][3] - mx2);
    }
    s1 += __shfl_xor_sync(0xffffffffu, s1, 1);
    s1 += __shfl_xor_sync(0xffffffffu, s1, 2);
    s2 += __shfl_xor_sync(0xffffffffu, s2, 1);
    s2 += __shfl_xor_sync(0xffffffffu, s2, 2);
    const float i1 = 1.f / s1, i2 = 1.f / s2;
    const float m1 = mu[r1], m2 = mu[r1 + 8];

    // ---- epilogue A: Sc/cov to gmem; L replaces G in acc (C-fragment layout) ----
    {
        const size_t ob = (size_t)bm << 14;
        #pragma unroll
        for (int n = 0; n < 16; n++) {
            int col = 8 * n + 2 * tg;
            float2 mc = *(float2*)(mu + col);
            float sc0 = __expf(acc[n][0] - mx1) * i1;
            float sc1 = __expf(acc[n][1] - mx1) * i1;
            float sc2 = __expf(acc[n][2] - mx2) * i2;
            float sc3 = __expf(acc[n][3] - mx2) * i2;
            float cv0 = acc[n][0] * (1.f / 49.f) - m1 * mc.x;
            float cv1 = acc[n][1] * (1.f / 49.f) - m1 * mc.y;
            float cv2 = acc[n][2] * (1.f / 49.f) - m2 * mc.x;
            float cv3 = acc[n][3] * (1.f / 49.f) - m2 * mc.y;
            *(float2*)(Sc  + ob + (size_t)r1 * 128 + col)       = make_float2(sc0, sc1);
            *(float2*)(Sc  + ob + (size_t)(r1 + 8) * 128 + col) = make_float2(sc2, sc3);
            *(float2*)(cov + ob + (size_t)r1 * 128 + col)       = make_float2(cv0, cv1);
            *(float2*)(cov + ob + (size_t)(r1 + 8) * 128 + col) = make_float2(cv2, cv3);
            acc[n][0] = fmaf(ALPHA, cv0, sc0);
            acc[n][1] = fmaf(ALPHA, cv1, sc1);
            acc[n][2] = fmaf(ALPHA, cv2, sc2);
            acc[n][3] = fmaf(ALPHA, cv3, sc3);
        }
    }

    // ---- GEMM2: Ec = L * F, 8 K16 tiles. A fragments direct from acc (no shuffles) ----
    float acc2[7][4];
    #pragma unroll
    for (int n = 0; n < 7; n++)
        #pragma unroll
        for (int j = 0; j < 4; j++) acc2[n][j] = 0.f;

    #pragma unroll
    for (int kk = 0; kk < 8; kk++) {
        // split-0 fragments
        uint32_t a0 = packbf(acc[2*kk][0],     acc[2*kk][1]);
        uint32_t a1 = packbf(acc[2*kk][2],     acc[2*kk][3]);
        uint32_t a2 = packbf(acc[2*kk + 1][0], acc[2*kk + 1][1]);
        uint32_t a3 = packbf(acc[2*kk + 1][2], acc[2*kk + 1][3]);
        // split-1 (residual) fragments
        uint32_t r0 = packbf(acc[2*kk][0] - lof(a0),     acc[2*kk][1] - hif(a0));
        uint32_t r1f = packbf(acc[2*kk][2] - lof(a1),    acc[2*kk][3] - hif(a1));
        uint32_t r2 = packbf(acc[2*kk + 1][0] - lof(a2), acc[2*kk + 1][1] - hif(a2));
        uint32_t r3 = packbf(acc[2*kk + 1][2] - lof(a3), acc[2*kk + 1][3] - hif(a3));
        const int kb = 8 * kk + tg;   // u32 index within Ft row
        #pragma unroll
        for (int n = 0; n < 7; n++) {
            const int bb = (8 * n + g) * STW + kb;
            uint32_t b00 = T0w[bb], b01 = T0w[bb + 4];
            uint32_t b10 = T1w[bb], b11 = T1w[bb + 4];
            mma16(acc2[n], a0, a1, a2, a3, b00, b01);
            mma16(acc2[n], a0, a1, a2, a3, b10, b11);
            mma16(acc2[n], r0, r1f, r2, r3, b00, b01);
        }
    }

    // ---- epilogue B: fold Ec, out = x * (beta*Ec + x) ----
    {
        const float beta0 = beta[0];
        #pragma unroll
        for (int n = 0; n < 7; n++) {
            const int p0 = 8 * n + 2 * tg;
            #pragma unroll
            for (int e = 0; e < 4; e++) {
                int p = p0 + (e & 1);
                int c = (e < 2) ? r1 : (r1 + 8);
                if (p < PP) {
                    float xv = bf2f(Fb0[c * FSB + p]) + bf2f(Fb1[c * FSB + p]);
                    float ec = acc2[n][e];
                    int i = p / PHW, j = p - i * PHW;
                    size_t ga = xoff + (size_t)c * (HW * HW) + i * HW + j;
                    ecmap[ga] = ec;
                    out[ga]   = xv * fmaf(beta0, ec, xv);
                }
            }
        }
    }
}

extern "C" void kernel_launch(void* const* d_in, const int* in_sizes, int n_in,
                              void* d_out, int out_size)
{
    const float* x    = (const float*)d_in[0];
    const float* beta = (const float*)d_in[1];

    float* out   = (float*)d_out;
    float* Sc    = out + N_OUT;
    float* cov   = Sc + N_SCC;
    float* ecmap = cov + N_SCC;

    cudaFuncSetAttribute(bdca_mma_kernel, cudaFuncAttributeMaxDynamicSharedMemorySize, SMEM_BYTES);
    bdca_mma_kernel<<<BB * 1024, 256, SMEM_BYTES>>>(x, beta, out, Sc, cov, ecmap);
}